// round 7
// baseline (speedup 1.0000x reference)
#include <cuda_runtime.h>
#include <cstdint>

// y[N] = x[N,H] @ w[H] + bias,  w[h] = FP4_TABLE[codes[h]] * absmax[h>>6]
// N = 32768, H = 4096. HBM-streaming GEMV.
//
// R6 diagnosis: ptxas register-minimization (targeting max occupancy) recycles
// 2 load buffers -> MLP~2/warp -> ~3MB in flight -> ~4.8TB/s, across ALL prior
// structurings. Fix: __launch_bounds__(256,3) raises the per-thread register
// budget to ~85, letting ptxas keep the 8-deep float4 staging batch live
// (MLP=8/warp; 24 warps/SM x 4KB = 96KB in flight per SM).

#define H_DIM 4096
#define ROWS_PER_BLOCK 8          // 8 warps * 1 row/warp
#define THREADS (ROWS_PER_BLOCK * 32)

__device__ __constant__ float c_fp4_tab[16] = {
    0.0f, 0.0052083333f, 0.6666667f, 1.0f, 0.3333333f, 0.5f, 0.16666667f, 0.25f,
    -0.0f, -0.0052083333f, -0.6666667f, -1.0f, -0.3333333f, -0.5f, -0.16666667f, -0.25f
};

__global__ __launch_bounds__(THREADS, 3)   // min 3 CTAs/SM -> ~85-reg budget for ptxas
void fp4_gemv_kernel(const float* __restrict__ x,
                     const int*   __restrict__ codes,
                     const float* __restrict__ absmax,
                     const float* __restrict__ bias,
                     float*       __restrict__ y,
                     int N)
{
    __shared__ float w_s[H_DIM];

    // Dequantize the tiny weight vector into shared memory once per block.
    // codes/absmax are 16KB/256B — L2-resident across all blocks.
    for (int i = threadIdx.x; i < H_DIM; i += THREADS) {
        w_s[i] = c_fp4_tab[codes[i] & 15] * absmax[i >> 6];
    }

    const float b = __ldg(bias);   // hoisted off the epilogue critical path
    __syncthreads();

    const int warp = threadIdx.x >> 5;
    const int lane = threadIdx.x & 31;
    const int row  = blockIdx.x * ROWS_PER_BLOCK + warp;
    if (row >= N) return;

    const float4* __restrict__ xr = reinterpret_cast<const float4*>(x + (size_t)row * H_DIM);
    const float4* __restrict__ ws = reinterpret_cast<const float4*>(w_s);

    // 1024 float4 per row; 32 per lane, processed as 4 groups of 8.
    // Stage all 8 loads of a group into registers BEFORE any FMA; with the
    // raised register budget ptxas should keep all 8 LDG.E.128 in flight.
    float acc0 = 0.0f, acc1 = 0.0f;

    #pragma unroll
    for (int g = 0; g < 4; g++) {
        float4 xv[8];
        #pragma unroll
        for (int j = 0; j < 8; j++) {
            xv[j] = __ldcs(&xr[g * 256 + j * 32 + lane]);   // evict-first: x is read-once
        }
        #pragma unroll
        for (int j = 0; j < 8; j++) {
            float4 wv = ws[g * 256 + j * 32 + lane];
            acc0 = fmaf(xv[j].x, wv.x, acc0);
            acc1 = fmaf(xv[j].y, wv.y, acc1);
            acc0 = fmaf(xv[j].z, wv.z, acc0);
            acc1 = fmaf(xv[j].w, wv.w, acc1);
        }
    }
    float acc = acc0 + acc1;

    // Warp reduction
    #pragma unroll
    for (int off = 16; off > 0; off >>= 1)
        acc += __shfl_xor_sync(0xFFFFFFFFu, acc, off);

    if (lane == 0)
        y[row] = acc + b;
}

extern "C" void kernel_launch(void* const* d_in, const int* in_sizes, int n_in,
                              void* d_out, int out_size)
{
    const float* x      = (const float*)d_in[0];   // [N, H] fp32
    const int*   codes  = (const int*)  d_in[1];   // [1, H] int32
    const float* absmax = (const float*)d_in[2];   // [1, H/64] fp32
    const float* bias   = (const float*)d_in[3];   // [1] fp32
    float*       y      = (float*)d_out;           // [N, 1] fp32

    const int N = in_sizes[0] / H_DIM;             // 32768
    const int grid = (N + ROWS_PER_BLOCK - 1) / ROWS_PER_BLOCK;

    fp4_gemv_kernel<<<grid, THREADS>>>(x, codes, absmax, bias, y, N);
}

// round 8
// speedup vs baseline: 1.3602x; 1.3602x over previous
#include <cuda_runtime.h>
#include <cstdint>

// y[N] = x[N,H] @ w[H] + bias,  w[h] = FP4_TABLE[codes[h]] * absmax[h>>6]
// N = 32768, H = 4096.
//
// R7 conclusion: all load-engine variants (MLP 2..8, cp.async pipeline) hit the
// same ~4.6-5.0 TB/s band -> pattern-level DRAM service ceiling, not an MLP
// deficit. So: strip every non-streaming cost. Weight dequant moves to a tiny
// one-shot kernel writing a __device__ global; the GEMV kernel has NO smem,
// NO syncthreads, NO per-block preamble — pure x streaming, w from L1/L2.

#define H_DIM 4096
#define RPB   8                      // rows per block, 1 per warp
#define THREADS (RPB * 32)

__device__ float g_w[H_DIM];         // dequantized weight scratch (legal __device__ global)

__device__ __constant__ float c_fp4_tab[16] = {
    0.0f, 0.0052083333f, 0.6666667f, 1.0f, 0.3333333f, 0.5f, 0.16666667f, 0.25f,
    -0.0f, -0.0052083333f, -0.6666667f, -1.0f, -0.3333333f, -0.5f, -0.16666667f, -0.25f
};

__global__ void fp4_dequant_kernel(const int* __restrict__ codes,
                                   const float* __restrict__ absmax)
{
    int i = blockIdx.x * blockDim.x + threadIdx.x;
    if (i < H_DIM)
        g_w[i] = c_fp4_tab[codes[i] & 15] * absmax[i >> 6];
}

__global__ __launch_bounds__(THREADS)
void fp4_gemv_kernel(const float* __restrict__ x,
                     const float* __restrict__ bias,
                     float*       __restrict__ y,
                     int N)
{
    const int warp = threadIdx.x >> 5;
    const int lane = threadIdx.x & 31;
    const int row  = blockIdx.x * RPB + warp;
    if (row >= N) return;

    const float4* __restrict__ xr = reinterpret_cast<const float4*>(x + (size_t)row * H_DIM);
    const float4* __restrict__ wr = reinterpret_cast<const float4*>(g_w);
    const float b = __ldg(bias);

    // 1024 float4 per row; 32 per lane as 4 groups of 8 (structure of the
    // best-so-far R3 kernel, minus smem/sync/preamble).
    float acc0 = 0.0f, acc1 = 0.0f;

    #pragma unroll
    for (int g = 0; g < 4; g++) {
        float4 xv[8];
        #pragma unroll
        for (int j = 0; j < 8; j++) {
            xv[j] = __ldcs(&xr[g * 256 + j * 32 + lane]);   // evict-first: x is read-once
        }
        #pragma unroll
        for (int j = 0; j < 8; j++) {
            float4 wv = __ldg(&wr[g * 256 + j * 32 + lane]); // 16KB, L1-resident after CTA 1
            acc0 = fmaf(xv[j].x, wv.x, acc0);
            acc1 = fmaf(xv[j].y, wv.y, acc1);
            acc0 = fmaf(xv[j].z, wv.z, acc0);
            acc1 = fmaf(xv[j].w, wv.w, acc1);
        }
    }
    float acc = acc0 + acc1;

    #pragma unroll
    for (int off = 16; off > 0; off >>= 1)
        acc += __shfl_xor_sync(0xFFFFFFFFu, acc, off);

    if (lane == 0)
        y[row] = acc + b;
}

extern "C" void kernel_launch(void* const* d_in, const int* in_sizes, int n_in,
                              void* d_out, int out_size)
{
    const float* x      = (const float*)d_in[0];   // [N, H] fp32
    const int*   codes  = (const int*)  d_in[1];   // [1, H] int32
    const float* absmax = (const float*)d_in[2];   // [1, H/64] fp32
    const float* bias   = (const float*)d_in[3];   // [1] fp32
    float*       y      = (float*)d_out;           // [N, 1] fp32

    const int N = in_sizes[0] / H_DIM;             // 32768

    // One-shot weight dequant (stream-ordered before the GEMV; graph-capturable).
    fp4_dequant_kernel<<<(H_DIM + 255) / 256, 256>>>(codes, absmax);

    const int grid = (N + RPB - 1) / RPB;
    fp4_gemv_kernel<<<grid, THREADS>>>(x, bias, y, N);
}

// round 9
// speedup vs baseline: 1.3638x; 1.0027x over previous
#include <cuda_runtime.h>
#include <cstdint>

// y[N] = x[N,H] @ w[H] + bias,  w[h] = FP4_TABLE[codes[h]] * absmax[h>>6]
// N = 32768, H = 4096.
//
// R8 established: no smem / no barrier / no per-block preamble -> 80% DRAM.
// R9 change: x loads widened to 256-bit (ld.global.cs.v8.f32, sm_100a
// LDG.E.256) — doubles bytes-in-flight per scoreboard slot at identical
// register/occupancy cost, halves LDG issue count.

#define H_DIM 4096
#define RPB   8                      // rows per block, 1 per warp
#define THREADS (RPB * 32)

__device__ float g_w[H_DIM];         // dequantized weight scratch

__device__ __constant__ float c_fp4_tab[16] = {
    0.0f, 0.0052083333f, 0.6666667f, 1.0f, 0.3333333f, 0.5f, 0.16666667f, 0.25f,
    -0.0f, -0.0052083333f, -0.6666667f, -1.0f, -0.3333333f, -0.5f, -0.16666667f, -0.25f
};

__global__ void fp4_dequant_kernel(const int* __restrict__ codes,
                                   const float* __restrict__ absmax)
{
    int i = blockIdx.x * blockDim.x + threadIdx.x;
    if (i < H_DIM)
        g_w[i] = c_fp4_tab[codes[i] & 15] * absmax[i >> 6];
}

// 256-bit streaming load (sm_100a): one LDG.E.256, 32B per lane.
__device__ __forceinline__ void ldg_cs_f8(const float* p, float4& a, float4& b) {
    asm("ld.global.cs.v8.f32 {%0,%1,%2,%3,%4,%5,%6,%7}, [%8];"
        : "=f"(a.x), "=f"(a.y), "=f"(a.z), "=f"(a.w),
          "=f"(b.x), "=f"(b.y), "=f"(b.z), "=f"(b.w)
        : "l"(p));
}

__global__ __launch_bounds__(THREADS)
void fp4_gemv_kernel(const float* __restrict__ x,
                     const float* __restrict__ bias,
                     float*       __restrict__ y,
                     int N)
{
    const int warp = threadIdx.x >> 5;
    const int lane = threadIdx.x & 31;
    const int row  = blockIdx.x * RPB + warp;
    if (row >= N) return;

    const float* __restrict__ xr = x + (size_t)row * H_DIM;
    const float4* __restrict__ wr = reinterpret_cast<const float4*>(g_w);
    const float b = __ldg(bias);

    // 512 float8 per row -> 16 per lane, as 4 groups of 4.
    // Each group: 4 x LDG.E.256 staged, then FMAs against L1-resident w.
    float acc0 = 0.0f, acc1 = 0.0f;

    #pragma unroll
    for (int g = 0; g < 4; g++) {
        float4 xa[4], xb[4];
        #pragma unroll
        for (int j = 0; j < 4; j++) {
            // float8 index: g*128 + j*32 + lane ; byte offset = idx*32
            ldg_cs_f8(xr + (size_t)(g * 128 + j * 32 + lane) * 8, xa[j], xb[j]);
        }
        #pragma unroll
        for (int j = 0; j < 4; j++) {
            int f4 = (g * 128 + j * 32 + lane) * 2;   // float4 index of xa
            float4 wa = __ldg(&wr[f4]);
            float4 wb = __ldg(&wr[f4 + 1]);
            acc0 = fmaf(xa[j].x, wa.x, acc0);
            acc1 = fmaf(xa[j].y, wa.y, acc1);
            acc0 = fmaf(xa[j].z, wa.z, acc0);
            acc1 = fmaf(xa[j].w, wa.w, acc1);
            acc0 = fmaf(xb[j].x, wb.x, acc0);
            acc1 = fmaf(xb[j].y, wb.y, acc1);
            acc0 = fmaf(xb[j].z, wb.z, acc0);
            acc1 = fmaf(xb[j].w, wb.w, acc1);
        }
    }
    float acc = acc0 + acc1;

    #pragma unroll
    for (int off = 16; off > 0; off >>= 1)
        acc += __shfl_xor_sync(0xFFFFFFFFu, acc, off);

    if (lane == 0)
        y[row] = acc + b;
}

extern "C" void kernel_launch(void* const* d_in, const int* in_sizes, int n_in,
                              void* d_out, int out_size)
{
    const float* x      = (const float*)d_in[0];   // [N, H] fp32
    const int*   codes  = (const int*)  d_in[1];   // [1, H] int32
    const float* absmax = (const float*)d_in[2];   // [1, H/64] fp32
    const float* bias   = (const float*)d_in[3];   // [1] fp32
    float*       y      = (float*)d_out;           // [N, 1] fp32

    const int N = in_sizes[0] / H_DIM;             // 32768

    fp4_dequant_kernel<<<(H_DIM + 255) / 256, 256>>>(codes, absmax);

    const int grid = (N + RPB - 1) / RPB;
    fp4_gemv_kernel<<<grid, THREADS>>>(x, bias, y, N);
}